// round 11
// baseline (speedup 1.0000x reference)
#include <cuda_runtime.h>
#include <cuda_fp16.h>
#include <mma.h>
#include <stdint.h>
using namespace nvcuda;

#define N_NODES 100000
#define N_EDGES 1600000
#define N_GRAPH 64
#define HID 128
#define IN_C 4
#define ELL_CAP 64
#define N_PAD ((N_NODES + 127) & ~127)   // 100096

// ---------------- scratch ----------------
__device__ __half g_h16A[(size_t)N_PAD * HID];    // h3
__device__ __half g_h16B[(size_t)N_PAD * HID];    // g2
__device__ int    g_ell[(size_t)N_NODES * ELL_CAP];  // 25.6 MB
__device__ int    g_cnt[N_NODES];                 // in-degree (atomic cursor)
__device__ float  g_dinv[N_NODES];
__device__ float4 g_pf[N_NODES];                  // fp32x4: dinv*x
__device__ float4 g_agg[N_NODES];                 // aggregated, dinv-scaled
__device__ int    g_is64;

// ---------------- dtype detection ----------------
__global__ void k_detect(const int* ei32) {
    int t = threadIdx.x;
    int z = (ei32[2 * t + 1] == 0);
    unsigned m = __ballot_sync(0xFFFFFFFFu, z);
    __shared__ int ok[2];
    if ((t & 31) == 0) ok[t >> 5] = (m == 0xFFFFFFFFu);
    __syncthreads();
    if (t == 0) g_is64 = ok[0] & ok[1];
}

__device__ __forceinline__ int load_idx(const void* p, long long i) {
    if (g_is64) return (int)((const long long*)p)[i];
    return ((const int*)p)[i];
}

// ---------------- single-pass ELL build (4 edges / thread) ----------------
__global__ void k_fill_ell(const void* ei) {
    int t = blockIdx.x * blockDim.x + threadIdx.x;
    if (t >= N_EDGES / 4) return;
    int s[4], d[4];
    if (g_is64) {
        const longlong2* p64 = (const longlong2*)ei;
        longlong2 ps0 = __ldg(&p64[2 * t]);
        longlong2 ps1 = __ldg(&p64[2 * t + 1]);
        longlong2 pd0 = __ldg(&p64[N_EDGES / 2 + 2 * t]);
        longlong2 pd1 = __ldg(&p64[N_EDGES / 2 + 2 * t + 1]);
        s[0] = (int)ps0.x; s[1] = (int)ps0.y; s[2] = (int)ps1.x; s[3] = (int)ps1.y;
        d[0] = (int)pd0.x; d[1] = (int)pd0.y; d[2] = (int)pd1.x; d[3] = (int)pd1.y;
    } else {
        const int4* p32 = (const int4*)ei;
        int4 ps = __ldg(&p32[t]);
        int4 pd = __ldg(&p32[N_EDGES / 4 + t]);
        s[0] = ps.x; s[1] = ps.y; s[2] = ps.z; s[3] = ps.w;
        d[0] = pd.x; d[1] = pd.y; d[2] = pd.z; d[3] = pd.w;
    }
    #pragma unroll
    for (int k = 0; k < 4; ++k) {
        int pos = atomicAdd(&g_cnt[d[k]], 1);
        if (pos < ELL_CAP) g_ell[(size_t)d[k] * ELL_CAP + pos] = s[k];
    }
}

// ---------------- pre: dinv + p = fp32x4(dinv * x) ----------------
__global__ void k_pre(const float* __restrict__ x) {
    int v = blockIdx.x * blockDim.x + threadIdx.x;
    if (v >= N_NODES) return;
    float dv = rsqrtf((float)(g_cnt[v] + 1));   // +1 self loop
    g_dinv[v] = dv;
    float4 xv = __ldg(&((const float4*)x)[v]);
    float4 p;
    p.x = dv * xv.x; p.y = dv * xv.y; p.z = dv * xv.z; p.w = dv * xv.w;
    g_pf[v] = p;
}

// ---------------- layer-1 aggregation: 4 lanes per node ----------------
__global__ void k_agg1() {
    int tid = blockIdx.x * blockDim.x + threadIdx.x;
    int v = tid >> 2, qr = tid & 3;
    bool active = (v < N_NODES);
    int deg = active ? min(g_cnt[v], ELL_CAP) : 0;
    float4 acc = make_float4(0.0f, 0.0f, 0.0f, 0.0f);
    if (active) {
        const int4* row4 = (const int4*)(g_ell + (size_t)v * ELL_CAP);
        int nq = (deg + 3) >> 2;
        for (int q = qr; q < nq; q += 4) {
            int4 s = __ldg(&row4[q]);
            int base = q << 2;
            if (base + 0 < deg) { float4 t = __ldg(&g_pf[s.x]); acc.x += t.x; acc.y += t.y; acc.z += t.z; acc.w += t.w; }
            if (base + 1 < deg) { float4 t = __ldg(&g_pf[s.y]); acc.x += t.x; acc.y += t.y; acc.z += t.z; acc.w += t.w; }
            if (base + 2 < deg) { float4 t = __ldg(&g_pf[s.z]); acc.x += t.x; acc.y += t.y; acc.z += t.z; acc.w += t.w; }
            if (base + 3 < deg) { float4 t = __ldg(&g_pf[s.w]); acc.x += t.x; acc.y += t.y; acc.z += t.z; acc.w += t.w; }
        }
    }
    // reduce across the 4 lanes of this node (lanes differ only in qr)
    #pragma unroll
    for (int o = 1; o < 4; o <<= 1) {
        acc.x += __shfl_xor_sync(0xFFFFFFFFu, acc.x, o);
        acc.y += __shfl_xor_sync(0xFFFFFFFFu, acc.y, o);
        acc.z += __shfl_xor_sync(0xFFFFFFFFu, acc.z, o);
        acc.w += __shfl_xor_sync(0xFFFFFFFFu, acc.w, o);
    }
    if (active && qr == 0) {
        float4 self = g_pf[v];                   // self loop
        float dv = g_dinv[v];
        float4 o;
        o.x = dv * (acc.x + self.x);
        o.y = dv * (acc.y + self.y);
        o.z = dv * (acc.z + self.z);
        o.w = dv * (acc.w + self.w);
        g_agg[v] = o;
    }
}

// ---------------- fused layer-1 transform + GEMM ----------------
// Per 128-row tile: h2 = relu(agg @ W1 + b1) computed into smem (fp16),
// then g2 = fp16(dinv * (h2 @ W2)) via wmma. h2 never touches global memory.
#define MM_PITCH 136
__global__ void k_l1gemm(const float* __restrict__ W1, const float* __restrict__ b1,
                         const float* __restrict__ W2, __half* __restrict__ outh) {
    extern __shared__ char smraw[];
    __half* W2h = (__half*)smraw;                          // [128][MM_PITCH] fp16
    __half* h2s = W2h + HID * MM_PITCH;                    // [128][MM_PITCH] fp16
    float* stage = (float*)(h2s + HID * MM_PITCH);         // [8][16][MM_PITCH] fp32
    float* W1s = stage + 8 * 16 * MM_PITCH;                // [4][128] fp32
    float* b1s = W1s + IN_C * HID;                         // [128] fp32
    int t = threadIdx.x;
    int warp = t >> 5, lane = t & 31;
    for (int i = t; i < HID * HID; i += 256) {
        int r = i >> 7, c = i & 127;
        W2h[r * MM_PITCH + c] = __float2half(W2[i]);
    }
    for (int i = t; i < IN_C * HID; i += 256) W1s[i] = W1[i];
    if (t < HID) b1s[t] = b1[t];
    __syncthreads();

    float* st = stage + warp * 16 * MM_PITCH;
    const int ntiles = N_PAD / 128;   // 782
    for (int tile = blockIdx.x; tile < ntiles; tile += gridDim.x) {
        int row0 = tile * 128;
        // --- compute h2 tile into smem (all warps finished reading h2s of prev tile) ---
        for (int i = t; i < 128 * HID; i += 256) {
            int r = i >> 7, c = i & 127;
            int row = row0 + r;
            float val = 0.0f;
            if (row < N_NODES) {
                float4 a = __ldg(&g_agg[row]);   // warp-uniform -> broadcast
                val = fmaxf(a.x * W1s[c] + a.y * W1s[HID + c]
                          + a.z * W1s[2 * HID + c] + a.w * W1s[3 * HID + c] + b1s[c], 0.0f);
            }
            h2s[r * MM_PITCH + c] = __float2half(val);
        }
        __syncthreads();
        // --- wmma: warp computes rows [warp*16, warp*16+16) x 128 cols ---
        wmma::fragment<wmma::accumulator, 16, 16, 16, float> c[8];
        #pragma unroll
        for (int n = 0; n < 8; ++n) wmma::fill_fragment(c[n], 0.0f);
        #pragma unroll
        for (int k0 = 0; k0 < HID; k0 += 16) {
            wmma::fragment<wmma::matrix_a, 16, 16, 16, __half, wmma::row_major> a;
            wmma::load_matrix_sync(a, h2s + (warp * 16) * MM_PITCH + k0, MM_PITCH);
            #pragma unroll
            for (int n = 0; n < 8; ++n) {
                wmma::fragment<wmma::matrix_b, 16, 16, 16, __half, wmma::row_major> b;
                wmma::load_matrix_sync(b, W2h + k0 * MM_PITCH + n * 16, MM_PITCH);
                wmma::mma_sync(c[n], a, b, c[n]);
            }
        }
        #pragma unroll
        for (int n = 0; n < 8; ++n)
            wmma::store_matrix_sync(st + n * 16, c[n], MM_PITCH, wmma::mem_row_major);
        __syncwarp();
        #pragma unroll
        for (int r = 0; r < 16; ++r) {
            int row = row0 + warp * 16 + r;
            if (row < N_NODES) {
                float dv = g_dinv[row];
                float4 v = *(const float4*)&st[r * MM_PITCH + lane * 4];
                __half2 p0 = __floats2half2_rn(dv * v.x, dv * v.y);
                __half2 p1 = __floats2half2_rn(dv * v.z, dv * v.w);
                uint2 u;
                u.x = *(const unsigned*)&p0;
                u.y = *(const unsigned*)&p1;
                *(uint2*)&outh[(size_t)row * HID + lane * 4] = u;
            }
        }
        __syncthreads();   // all readers of h2s done before next tile's fill
    }
}

// ---------------- layer-2 gather: h3 = relu(dinv*agg(g2) + b2), fp16 out ----------------
__device__ __forceinline__ void acc8(float* a, uint4 u) {
    float2 f0 = __half22float2(*(const __half2*)&u.x);
    float2 f1 = __half22float2(*(const __half2*)&u.y);
    float2 f2 = __half22float2(*(const __half2*)&u.z);
    float2 f3 = __half22float2(*(const __half2*)&u.w);
    a[0] += f0.x; a[1] += f0.y; a[2] += f1.x; a[3] += f1.y;
    a[4] += f2.x; a[5] += f2.y; a[6] += f3.x; a[7] += f3.y;
}

__global__ void k_gather2(const __half* __restrict__ gin, const float* __restrict__ bias,
                          __half* __restrict__ gout) {
    int v = (blockIdx.x * blockDim.x + threadIdx.x) >> 5;
    int lane = threadIdx.x & 31;
    if (v >= N_NODES) return;
    int hf = lane >> 4, sub = lane & 15;
    const uint4* gin4 = (const uint4*)gin;     // 16 uint4 per node row
    float a[8];
    #pragma unroll
    for (int k = 0; k < 8; ++k) a[k] = 0.0f;
    int deg = min(g_cnt[v], ELL_CAP);
    const int* row = g_ell + (size_t)v * ELL_CAP;
    int j = hf;
    for (; j + 6 < deg; j += 8) {
        int s0 = __ldg(&row[j]);
        int s1 = __ldg(&row[j + 2]);
        int s2 = __ldg(&row[j + 4]);
        int s3 = __ldg(&row[j + 6]);
        uint4 u0 = __ldg(&gin4[(size_t)s0 * 16 + sub]);
        uint4 u1 = __ldg(&gin4[(size_t)s1 * 16 + sub]);
        uint4 u2 = __ldg(&gin4[(size_t)s2 * 16 + sub]);
        uint4 u3 = __ldg(&gin4[(size_t)s3 * 16 + sub]);
        acc8(a, u0); acc8(a, u1); acc8(a, u2); acc8(a, u3);
    }
    for (; j < deg; j += 2) {
        int s0 = __ldg(&row[j]);
        uint4 u0 = __ldg(&gin4[(size_t)s0 * 16 + sub]);
        acc8(a, u0);
    }
    __syncwarp();
    #pragma unroll
    for (int k = 0; k < 8; ++k) a[k] += __shfl_xor_sync(0xFFFFFFFFu, a[k], 16);
    if (hf == 0) {
        uint4 us = __ldg(&gin4[(size_t)v * 16 + sub]);   // self loop
        acc8(a, us);
        float dv = g_dinv[v];
        const float4* b4 = (const float4*)bias;
        float4 bb0 = __ldg(&b4[sub * 2]);
        float4 bb1 = __ldg(&b4[sub * 2 + 1]);
        __half2 p0 = __floats2half2_rn(fmaxf(dv * a[0] + bb0.x, 0.0f),
                                       fmaxf(dv * a[1] + bb0.y, 0.0f));
        __half2 p1 = __floats2half2_rn(fmaxf(dv * a[2] + bb0.z, 0.0f),
                                       fmaxf(dv * a[3] + bb0.w, 0.0f));
        __half2 p2 = __floats2half2_rn(fmaxf(dv * a[4] + bb1.x, 0.0f),
                                       fmaxf(dv * a[5] + bb1.y, 0.0f));
        __half2 p3 = __floats2half2_rn(fmaxf(dv * a[6] + bb1.z, 0.0f),
                                       fmaxf(dv * a[7] + bb1.w, 0.0f));
        uint4 o;
        o.x = *(const unsigned*)&p0;
        o.y = *(const unsigned*)&p1;
        o.z = *(const unsigned*)&p2;
        o.w = *(const unsigned*)&p3;
        ((uint4*)gout)[(size_t)v * 16 + sub] = o;
    }
}

// ---------------- fused pool: bounds + mean, one block per graph ----------------
__global__ void k_poolmean(const __half* __restrict__ h, const void* batch,
                           float* __restrict__ outp) {
    int g = blockIdx.x;
    __shared__ int sb[2];
    if (threadIdx.x < 2) {
        int target = g + threadIdx.x;
        int lo = 0, hi = N_NODES;
        while (lo < hi) {
            int mid = (lo + hi) >> 1;
            if (load_idx(batch, mid) < target) lo = mid + 1; else hi = mid;
        }
        sb[threadIdx.x] = lo;
    }
    __syncthreads();
    int s = sb[0], e = sb[1];
    int stream = threadIdx.x >> 6;     // 16 row streams
    int c2 = threadIdx.x & 63;         // half2 column
    const __half2* h2p = (const __half2*)h;
    float2 acc = make_float2(0.0f, 0.0f);
    #pragma unroll 4
    for (int r = s + stream; r < e; r += 16) {
        float2 t = __half22float2(h2p[(size_t)r * 64 + c2]);
        acc.x += t.x; acc.y += t.y;
    }
    __shared__ float2 red[1024];
    red[threadIdx.x] = acc;
    __syncthreads();
    if (threadIdx.x < 64) {
        float2 a = make_float2(0.0f, 0.0f);
        #pragma unroll
        for (int k = 0; k < 16; ++k) {
            float2 t = red[k * 64 + threadIdx.x];
            a.x += t.x; a.y += t.y;
        }
        float inv = 1.0f / fmaxf((float)(e - s), 1.0f);
        outp[g * HID + c2 * 2]     = a.x * inv;
        outp[g * HID + c2 * 2 + 1] = a.y * inv;
    }
}

// ---------------- launch (single stream, linear chain) ----------------
extern "C" void kernel_launch(void* const* d_in, const int* in_sizes, int n_in,
                              void* d_out, int out_size) {
    const float* x  = (const float*)d_in[0];
    const void*  ei = d_in[1];
    const void*  batch = d_in[2];
    const float* W1 = (const float*)d_in[3];
    const float* b1 = (const float*)d_in[4];
    const float* W2 = (const float*)d_in[5];
    const float* b2 = (const float*)d_in[6];
    float* out = (float*)d_out;

    void* cntp;  cudaGetSymbolAddress(&cntp, g_cnt);
    void* h16Ap; cudaGetSymbolAddress(&h16Ap, g_h16A);
    void* h16Bp; cudaGetSymbolAddress(&h16Bp, g_h16B);

    static int smem_set = 0;
    const int l1_smem = 2 * HID * MM_PITCH * sizeof(__half)        // W2h + h2s
                      + 8 * 16 * MM_PITCH * sizeof(float)          // stage
                      + (IN_C * HID + HID) * sizeof(float);        // W1s + b1s
    if (!smem_set) {
        cudaFuncSetAttribute(k_l1gemm, cudaFuncAttributeMaxDynamicSharedMemorySize, l1_smem);
        smem_set = 1;
    }

    k_detect<<<1, 64>>>((const int*)ei);
    cudaMemsetAsync(cntp, 0, N_NODES * sizeof(int));

    const int EB4 = (N_EDGES / 4 + 255) / 256;
    k_fill_ell<<<EB4, 256>>>(ei);
    k_pre<<<(N_NODES + 255) / 256, 256>>>(x);
    k_agg1<<<(N_NODES * 4 + 255) / 256, 256>>>();
    k_l1gemm<<<296, 256, l1_smem>>>(W1, b1, W2, (__half*)h16Bp);                        // g2 -> B
    k_gather2<<<(N_NODES * 32 + 255) / 256, 256>>>((__half*)h16Bp, b2, (__half*)h16Ap); // h3 -> A
    k_poolmean<<<N_GRAPH, 1024>>>((__half*)h16Ap, batch, out);
}